// round 2
// baseline (speedup 1.0000x reference)
#include <cuda_runtime.h>

// ---------------------------------------------------------------------------
// MLMM electrostatics: E_atom[u] = E0[u] + sum_{pairs p with idx_u[p]==u} E(p)
// E(p) = KE * q_v * ( q_u*chi - chi^3*(r.mu) + chi^5*(sum(O*Q) - trO/3*trQ) )
// masked to d <= 10 A.
//
// Strategy:
//   prep kernel : init out = atomic_energies; pack per-ML-atom table
//                 {q, mu(3), Q(9), trQ} into 64B-aligned float4[4] structs
//                 (one gather = 4x LDG.128 = 2 L2 sectors, fully used).
//   pair kernel : 1 thread / pair, streaming loads coalesced, cutoff check
//                 before gathers, RED.F32 scatter onto out.
//
// NOTE: indices are int32 (JAX x64-disabled downgrades jnp.int64 -> int32).
// ---------------------------------------------------------------------------

#define NML_MAX 50000
#define KE_CONST 14.399645351950548f
#define CUTOFF_A 10.0f

// Packed ML-atom table: [q, mux, muy, muz | Q0..Q3 | Q4..Q7 | Q8, trQ, 0, 0]
__device__ float4 g_packed[NML_MAX * 4];

__global__ void mlmm_prep_kernel(const float* __restrict__ q_ml,
                                 const float* __restrict__ mu,
                                 const float* __restrict__ Q,
                                 const float* __restrict__ e0,
                                 float* __restrict__ out,
                                 int nml) {
    int u = blockIdx.x * blockDim.x + threadIdx.x;
    if (u >= nml) return;

    out[u] = e0[u];

    float m0 = mu[3 * u + 0];
    float m1 = mu[3 * u + 1];
    float m2 = mu[3 * u + 2];

    float Qv[9];
#pragma unroll
    for (int k = 0; k < 9; k++) Qv[k] = Q[9 * u + k];
    float trQ = Qv[0] + Qv[4] + Qv[8];

    g_packed[4 * u + 0] = make_float4(q_ml[u], m0, m1, m2);
    g_packed[4 * u + 1] = make_float4(Qv[0], Qv[1], Qv[2], Qv[3]);
    g_packed[4 * u + 2] = make_float4(Qv[4], Qv[5], Qv[6], Qv[7]);
    g_packed[4 * u + 3] = make_float4(Qv[8], trQ, 0.0f, 0.0f);
}

__global__ void __launch_bounds__(256)
mlmm_pair_kernel(const float* __restrict__ dist,
                 const float* __restrict__ vec,
                 const float* __restrict__ outer,
                 const int* __restrict__ idx_u,
                 const int* __restrict__ idx_v,
                 const float* __restrict__ q_mm,
                 float* __restrict__ out,
                 int n) {
    int i = blockIdx.x * blockDim.x + threadIdx.x;
    if (i >= n) return;

    float d = dist[i];
    if (d > CUTOFF_A) return;  // masked pairs: no gathers, no atomic

    int u = idx_u[i];
    int v = idx_v[i];

    // streaming per-pair geometry
    float r0 = vec[3 * i + 0];
    float r1 = vec[3 * i + 1];
    float r2 = vec[3 * i + 2];

    const float* op = outer + 9ll * i;
    float o0 = op[0], o1 = op[1], o2 = op[2];
    float o3 = op[3], o4 = op[4], o5 = op[5];
    float o6 = op[6], o7 = op[7], o8 = op[8];

    // gathered ML-atom multipoles (64B packed struct, L2-resident)
    float4 p0 = g_packed[4 * u + 0];
    float4 p1 = g_packed[4 * u + 1];
    float4 p2 = g_packed[4 * u + 2];
    float4 p3 = g_packed[4 * u + 3];

    float q_v = __ldg(q_mm + v);

    float chi  = __fdividef(1.0f, d);
    float chi2 = chi * chi;
    float chi3 = chi2 * chi;
    float chi5 = chi3 * chi2;

    // charge-charge
    float e = p0.x * chi;

    // dipole: - chi^3 * (r . mu)
    float dot_rm = r0 * p0.y + r1 * p0.z + r2 * p0.w;
    e -= chi3 * dot_rm;

    // quadrupole: + chi^5 * ( sum(O*Q) - (trO/3)*trQ )
    float dot9 = o0 * p1.x + o1 * p1.y + o2 * p1.z + o3 * p1.w
               + o4 * p2.x + o5 * p2.y + o6 * p2.z + o7 * p2.w
               + o8 * p3.x;
    float trO = o0 + o4 + o8;
    e += chi5 * (dot9 - (trO * (1.0f / 3.0f)) * p3.y);

    e *= KE_CONST * q_v;

    atomicAdd(out + u, e);
}

extern "C" void kernel_launch(void* const* d_in, const int* in_sizes, int n_in,
                              void* d_out, int out_size) {
    const float* q_ml  = (const float*)d_in[0];  // [NML]
    const float* q_mm  = (const float*)d_in[1];  // [NMM]
    const float* mu    = (const float*)d_in[2];  // [NML,3]
    const float* Q     = (const float*)d_in[3];  // [NML,3,3]
    const float* e0    = (const float*)d_in[4];  // [NML]
    const float* dist  = (const float*)d_in[5];  // [P]
    const float* vec   = (const float*)d_in[6];  // [P,3]
    const float* outer = (const float*)d_in[7];  // [P,3,3]
    const int*   idx_u = (const int*)d_in[8];    // [P] int32
    const int*   idx_v = (const int*)d_in[9];    // [P] int32

    float* out = (float*)d_out;

    int nml = in_sizes[0];
    int P   = in_sizes[5];

    {
        int threads = 256;
        int blocks  = (nml + threads - 1) / threads;
        mlmm_prep_kernel<<<blocks, threads>>>(q_ml, mu, Q, e0, out, nml);
    }
    {
        int threads = 256;
        int blocks  = (P + threads - 1) / threads;
        mlmm_pair_kernel<<<blocks, threads>>>(dist, vec, outer, idx_u, idx_v,
                                              q_mm, out, P);
    }
}

// round 3
// speedup vs baseline: 1.0882x; 1.0882x over previous
#include <cuda_runtime.h>

// ---------------------------------------------------------------------------
// MLMM electrostatics.
// E(p) = KE * q_v * ( q_u*chi - chi^3*(r.mu) + chi^5 * sum(O * Q') )
// where Q' = Q - (trQ/3) I  (traceless; Q'22 = -(Q'00+Q'11)), which absorbs
// the reference's traceless-outer construction exactly:
//   sum(O*Q) - (trO/3)*trQ == sum(O*Q').
//
// prep kernel : out = e0; pack {q, mu3, Q'8} as 3x float4 (48 B) per ML atom.
// pair kernel : smem-stage vec/outer with coalesced float4 loads (kills the
//               AoS stride-12/36 scalar-load wavefronts), cutoff before the
//               gathers, 3x LDG.128 gather, RED.F32 scatter.
// ---------------------------------------------------------------------------

#define NML_MAX 50000
#define KE_CONST 14.399645351950548f
#define CUTOFF_A 10.0f
#define BLK 256

// Packed ML-atom table: [q, mux, muy, muz | Q'00 Q'01 Q'02 Q'10 | Q'11 Q'12 Q'20 Q'21]
__device__ float4 g_packed[NML_MAX * 3];

__global__ void mlmm_prep_kernel(const float* __restrict__ q_ml,
                                 const float* __restrict__ mu,
                                 const float* __restrict__ Q,
                                 const float* __restrict__ e0,
                                 float* __restrict__ out,
                                 int nml) {
    int u = blockIdx.x * blockDim.x + threadIdx.x;
    if (u >= nml) return;

    out[u] = e0[u];

    float m0 = mu[3 * u + 0];
    float m1 = mu[3 * u + 1];
    float m2 = mu[3 * u + 2];

    float Qv[9];
#pragma unroll
    for (int k = 0; k < 9; k++) Qv[k] = Q[9 * u + k];
    float third_tr = (Qv[0] + Qv[4] + Qv[8]) * (1.0f / 3.0f);

    // traceless Q'
    float t00 = Qv[0] - third_tr;
    float t11 = Qv[4] - third_tr;

    g_packed[3 * u + 0] = make_float4(q_ml[u], m0, m1, m2);
    g_packed[3 * u + 1] = make_float4(t00, Qv[1], Qv[2], Qv[3]);
    g_packed[3 * u + 2] = make_float4(t11, Qv[5], Qv[6], Qv[7]);
}

__global__ void __launch_bounds__(BLK)
mlmm_pair_kernel(const float* __restrict__ dist,
                 const float* __restrict__ vec,
                 const float* __restrict__ outer,
                 const int* __restrict__ idx_u,
                 const int* __restrict__ idx_v,
                 const float* __restrict__ q_mm,
                 float* __restrict__ out,
                 int n) {
    __shared__ float s_vec[BLK * 3];
    __shared__ float s_out[BLK * 9];

    long long base = (long long)blockIdx.x * BLK;
    int cnt = n - (int)base;
    if (cnt > BLK) cnt = BLK;

    if (cnt == BLK) {
        // fully coalesced float4 staging (3*BLK and 9*BLK divisible by 4;
        // offsets base*12B / base*36B keep 16B alignment since base%256==0)
        const float4* v4 = (const float4*)(vec + 3 * base);
        float4*       sv = (float4*)s_vec;
#pragma unroll
        for (int t = threadIdx.x; t < BLK * 3 / 4; t += BLK) sv[t] = v4[t];

        const float4* o4 = (const float4*)(outer + 9 * base);
        float4*       so = (float4*)s_out;
#pragma unroll
        for (int t = threadIdx.x; t < BLK * 9 / 4; t += BLK) so[t] = o4[t];
    } else {
        for (int t = threadIdx.x; t < cnt * 3; t += BLK) s_vec[t] = vec[3 * base + t];
        for (int t = threadIdx.x; t < cnt * 9; t += BLK) s_out[t] = outer[9 * base + t];
    }
    __syncthreads();

    int lane = threadIdx.x;
    if (lane >= cnt) return;

    long long i = base + lane;
    float d = dist[i];
    if (d > CUTOFF_A) return;  // masked pairs: no gathers, no atomic

    int u = idx_u[i];
    int v = idx_v[i];

    // per-pair geometry from smem (strides 3 & 9: conflict-free)
    float r0 = s_vec[3 * lane + 0];
    float r1 = s_vec[3 * lane + 1];
    float r2 = s_vec[3 * lane + 2];

    const float* op = s_out + 9 * lane;
    float o00 = op[0], o01 = op[1], o02 = op[2];
    float o10 = op[3], o11 = op[4], o12 = op[5];
    float o20 = op[6], o21 = op[7], o22 = op[8];

    // gathered ML-atom multipoles (48 B packed record, L2-resident)
    float4 p0 = g_packed[3 * u + 0];  // q, mu
    float4 p1 = g_packed[3 * u + 1];  // Q'00 Q'01 Q'02 Q'10
    float4 p2 = g_packed[3 * u + 2];  // Q'11 Q'12 Q'20 Q'21

    float q_v = __ldg(q_mm + v);

    float chi  = __fdividef(1.0f, d);
    float chi2 = chi * chi;
    float chi3 = chi2 * chi;
    float chi5 = chi3 * chi2;

    // charge-charge
    float e = p0.x * chi;

    // dipole: - chi^3 * (r . mu)
    float dot_rm = r0 * p0.y + r1 * p0.z + r2 * p0.w;
    e -= chi3 * dot_rm;

    // quadrupole: + chi^5 * sum(O * Q'), with Q'22 = -(Q'00 + Q'11)
    float dot9 = p1.x * (o00 - o22)
               + p2.x * (o11 - o22)
               + p1.y * o01 + p1.z * o02 + p1.w * o10
               + p2.y * o12 + p2.z * o20 + p2.w * o21;
    e += chi5 * dot9;

    e *= KE_CONST * q_v;

    atomicAdd(out + u, e);
}

extern "C" void kernel_launch(void* const* d_in, const int* in_sizes, int n_in,
                              void* d_out, int out_size) {
    const float* q_ml  = (const float*)d_in[0];  // [NML]
    const float* q_mm  = (const float*)d_in[1];  // [NMM]
    const float* mu    = (const float*)d_in[2];  // [NML,3]
    const float* Q     = (const float*)d_in[3];  // [NML,3,3]
    const float* e0    = (const float*)d_in[4];  // [NML]
    const float* dist  = (const float*)d_in[5];  // [P]
    const float* vec   = (const float*)d_in[6];  // [P,3]
    const float* outer = (const float*)d_in[7];  // [P,3,3]
    const int*   idx_u = (const int*)d_in[8];    // [P] int32
    const int*   idx_v = (const int*)d_in[9];    // [P] int32

    float* out = (float*)d_out;

    int nml = in_sizes[0];
    int P   = in_sizes[5];

    {
        int threads = 256;
        int blocks  = (nml + threads - 1) / threads;
        mlmm_prep_kernel<<<blocks, threads>>>(q_ml, mu, Q, e0, out, nml);
    }
    {
        int blocks = (P + BLK - 1) / BLK;
        mlmm_pair_kernel<<<blocks, BLK>>>(dist, vec, outer, idx_u, idx_v,
                                          q_mm, out, P);
    }
}

// round 4
// speedup vs baseline: 1.2216x; 1.1226x over previous
#include <cuda_runtime.h>
#include <cuda_fp16.h>

// ---------------------------------------------------------------------------
// MLMM electrostatics.
// E(p) = KE * q_v * ( q_u*chi - chi^3*(r.mu) + chi^5 * sum(O * Q') )
// with Q' = Q - (trQ/3) I (traceless), Q'22 = -(Q'00+Q'11); identically
//   sum(O*Q) - (trO/3)*trQ == sum(O*Q').
//
// Gather record per ML atom: 32 bytes, 32B-aligned (ONE L2 sector):
//   float4 {q, mux, muy, muz}  |  8 x fp16 {Q'00,Q'01,Q'02,Q'10,Q'11,Q'12,Q'20,Q'21}
// -> 2x LDG.128 per pair instead of 3, gather L2 traffic 96B -> 32B.
// Quadrupole in fp16: ~3e-4 relative error, well under the 1e-3 tolerance.
//
// pair kernel: smem-stage vec/outer with coalesced float4 loads, cutoff check
// before gathers, RED.F32 scatter.
// ---------------------------------------------------------------------------

#define NML_MAX 50000
#define KE_CONST 14.399645351950548f
#define CUTOFF_A 10.0f
#define BLK 256

// [2*u]   : float4 {q, mu}
// [2*u+1] : 8 halves (Q' traceless components), reinterpreted
__device__ __align__(32) float4 g_packed[NML_MAX * 2];

__global__ void mlmm_prep_kernel(const float* __restrict__ q_ml,
                                 const float* __restrict__ mu,
                                 const float* __restrict__ Q,
                                 const float* __restrict__ e0,
                                 float* __restrict__ out,
                                 int nml) {
    int u = blockIdx.x * blockDim.x + threadIdx.x;
    if (u >= nml) return;

    out[u] = e0[u];

    float m0 = mu[3 * u + 0];
    float m1 = mu[3 * u + 1];
    float m2 = mu[3 * u + 2];

    float Qv[9];
#pragma unroll
    for (int k = 0; k < 9; k++) Qv[k] = Q[9 * u + k];
    float third_tr = (Qv[0] + Qv[4] + Qv[8]) * (1.0f / 3.0f);

    float t00 = Qv[0] - third_tr;
    float t11 = Qv[4] - third_tr;

    g_packed[2 * u + 0] = make_float4(q_ml[u], m0, m1, m2);

    // pack Q' as 4 x half2: [t00,Q01] [Q02,Q10] [t11,Q12] [Q20,Q21]
    __half2 h0 = __floats2half2_rn(t00,   Qv[1]);
    __half2 h1 = __floats2half2_rn(Qv[2], Qv[3]);
    __half2 h2 = __floats2half2_rn(t11,   Qv[5]);
    __half2 h3 = __floats2half2_rn(Qv[6], Qv[7]);

    uint4 packed;
    packed.x = *reinterpret_cast<unsigned int*>(&h0);
    packed.y = *reinterpret_cast<unsigned int*>(&h1);
    packed.z = *reinterpret_cast<unsigned int*>(&h2);
    packed.w = *reinterpret_cast<unsigned int*>(&h3);
    reinterpret_cast<uint4*>(g_packed)[2 * u + 1] = packed;
}

__global__ void __launch_bounds__(BLK)
mlmm_pair_kernel(const float* __restrict__ dist,
                 const float* __restrict__ vec,
                 const float* __restrict__ outer,
                 const int* __restrict__ idx_u,
                 const int* __restrict__ idx_v,
                 const float* __restrict__ q_mm,
                 float* __restrict__ out,
                 int n) {
    __shared__ float s_vec[BLK * 3];
    __shared__ float s_out[BLK * 9];

    long long base = (long long)blockIdx.x * BLK;
    int cnt = n - (int)base;
    if (cnt > BLK) cnt = BLK;

    if (cnt == BLK) {
        const float4* v4 = (const float4*)(vec + 3 * base);
        float4*       sv = (float4*)s_vec;
#pragma unroll
        for (int t = threadIdx.x; t < BLK * 3 / 4; t += BLK) sv[t] = v4[t];

        const float4* o4 = (const float4*)(outer + 9 * base);
        float4*       so = (float4*)s_out;
#pragma unroll
        for (int t = threadIdx.x; t < BLK * 9 / 4; t += BLK) so[t] = o4[t];
    } else {
        for (int t = threadIdx.x; t < cnt * 3; t += BLK) s_vec[t] = vec[3 * base + t];
        for (int t = threadIdx.x; t < cnt * 9; t += BLK) s_out[t] = outer[9 * base + t];
    }
    __syncthreads();

    int lane = threadIdx.x;
    if (lane >= cnt) return;

    long long i = base + lane;
    float d = dist[i];
    if (d > CUTOFF_A) return;  // masked pairs: no gathers, no atomic

    int u = idx_u[i];
    int v = idx_v[i];

    // gathered ML-atom multipoles: one 32B-aligned sector, 2x LDG.128
    float4 p0 = g_packed[2 * u + 0];
    uint4  ph = reinterpret_cast<const uint4*>(g_packed)[2 * u + 1];
    float  q_v = __ldg(q_mm + v);

    // per-pair geometry from smem (strides 3 & 9: conflict-free)
    float r0 = s_vec[3 * lane + 0];
    float r1 = s_vec[3 * lane + 1];
    float r2 = s_vec[3 * lane + 2];

    const float* op = s_out + 9 * lane;
    float o00 = op[0], o01 = op[1], o02 = op[2];
    float o10 = op[3], o11 = op[4], o12 = op[5];
    float o20 = op[6], o21 = op[7], o22 = op[8];

    float chi  = __fdividef(1.0f, d);
    float chi2 = chi * chi;
    float chi3 = chi2 * chi;
    float chi5 = chi3 * chi2;

    // charge-charge
    float e = p0.x * chi;

    // dipole: - chi^3 * (r . mu)
    float dot_rm = r0 * p0.y + r1 * p0.z + r2 * p0.w;
    e -= chi3 * dot_rm;

    // quadrupole: + chi^5 * sum(O * Q'), Q'22 = -(Q'00 + Q'11)
    float2 c0 = __half22float2(*reinterpret_cast<__half2*>(&ph.x)); // t00, Q01
    float2 c1 = __half22float2(*reinterpret_cast<__half2*>(&ph.y)); // Q02, Q10
    float2 c2 = __half22float2(*reinterpret_cast<__half2*>(&ph.z)); // t11, Q12
    float2 c3 = __half22float2(*reinterpret_cast<__half2*>(&ph.w)); // Q20, Q21

    float dot9 = c0.x * (o00 - o22)
               + c2.x * (o11 - o22)
               + c0.y * o01 + c1.x * o02 + c1.y * o10
               + c2.y * o12 + c3.x * o20 + c3.y * o21;
    e += chi5 * dot9;

    e *= KE_CONST * q_v;

    atomicAdd(out + u, e);
}

extern "C" void kernel_launch(void* const* d_in, const int* in_sizes, int n_in,
                              void* d_out, int out_size) {
    const float* q_ml  = (const float*)d_in[0];  // [NML]
    const float* q_mm  = (const float*)d_in[1];  // [NMM]
    const float* mu    = (const float*)d_in[2];  // [NML,3]
    const float* Q     = (const float*)d_in[3];  // [NML,3,3]
    const float* e0    = (const float*)d_in[4];  // [NML]
    const float* dist  = (const float*)d_in[5];  // [P]
    const float* vec   = (const float*)d_in[6];  // [P,3]
    const float* outer = (const float*)d_in[7];  // [P,3,3]
    const int*   idx_u = (const int*)d_in[8];    // [P] int32
    const int*   idx_v = (const int*)d_in[9];    // [P] int32

    float* out = (float*)d_out;

    int nml = in_sizes[0];
    int P   = in_sizes[5];

    {
        int threads = 256;
        int blocks  = (nml + threads - 1) / threads;
        mlmm_prep_kernel<<<blocks, threads>>>(q_ml, mu, Q, e0, out, nml);
    }
    {
        int blocks = (P + BLK - 1) / BLK;
        mlmm_pair_kernel<<<blocks, BLK>>>(dist, vec, outer, idx_u, idx_v,
                                          q_mm, out, P);
    }
}